// round 1
// baseline (speedup 1.0000x reference)
#include <cuda_runtime.h>
#include <cstdint>

// Problem constants (from reference):
//   src:   [E=800000, D=64] float32
//   index: [E] int64 (or int32 if JAX x64 was disabled — detected at runtime)
//   out:   [N=50000, D=64] float32, scatter-mean along dim 0
#define D_DIM 64
#define D_VEC 16            // D/4 float4 chunks per row
#define N_SEG 50000

__device__ int g_counts[N_SEG];
__device__ int g_is64;      // 1 if index is int64, 0 if int32

// ---------------------------------------------------------------------------
// vector reduction: red.global.add.v4.f32 (sm_90+), no return value
// ---------------------------------------------------------------------------
__device__ __forceinline__ void red_add_v4(float* addr, float4 v) {
    asm volatile("red.global.add.v4.f32 [%0], {%1, %2, %3, %4};"
                 :: "l"(addr), "f"(v.x), "f"(v.y), "f"(v.z), "f"(v.w)
                 : "memory");
}

// ---------------------------------------------------------------------------
// Detect index dtype. Interpreting int32 data as int64 packs two random
// indices per word; the hi half is then almost surely nonzero, pushing the
// value out of [0, N_SEG). 64 samples -> misdetect probability ~ (2e-5)^64.
// ---------------------------------------------------------------------------
__global__ void k_detect(const void* __restrict__ idxp) {
    const long long* p = (const long long*)idxp;
    int ok = 1;
    #pragma unroll 4
    for (int i = 0; i < 64; i++) {
        long long v = p[i];
        if (v < 0 || v >= (long long)N_SEG) { ok = 0; break; }
    }
    g_is64 = ok;
}

__global__ void k_zero_counts() {
    int t = blockIdx.x * blockDim.x + threadIdx.x;
    if (t < N_SEG) g_counts[t] = 0;
}

// ---------------------------------------------------------------------------
// Fused scatter: one thread per float4 chunk (E * 16 threads).
//   thread t: row = t >> 4, chunk = t & 15
//   vector RED into out[idx*64 + chunk*4 .. +3]
//   chunk 0 also bumps the per-segment count.
// ---------------------------------------------------------------------------
__global__ void __launch_bounds__(256) k_scatter(const float4* __restrict__ src4,
                                                 const void*   __restrict__ idxp,
                                                 float*        __restrict__ out,
                                                 int total /* = E*16 */) {
    int t = blockIdx.x * blockDim.x + threadIdx.x;
    if (t >= total) return;
    const int is64 = g_is64;
    int row = t >> 4;
    int c   = t & 15;

    int idx;
    if (is64) idx = (int)((const long long*)idxp)[row];
    else      idx = ((const int*)idxp)[row];

    float4 v = src4[t];                      // src4[row*16 + c] == src4[t]
    red_add_v4(out + (size_t)idx * D_DIM + c * 4, v);
    if (c == 0) atomicAdd(&g_counts[idx], 1);
}

// ---------------------------------------------------------------------------
// Normalize: out[row] /= max(count[row], 1). One thread per float4 chunk.
// ---------------------------------------------------------------------------
__global__ void __launch_bounds__(256) k_norm(float4* __restrict__ out4,
                                              int total /* = N*16 */) {
    int t = blockIdx.x * blockDim.x + threadIdx.x;
    if (t >= total) return;
    int row = t >> 4;
    int cnt = g_counts[row];
    float inv = 1.0f / (float)max(cnt, 1);
    float4 v = out4[t];
    v.x *= inv; v.y *= inv; v.z *= inv; v.w *= inv;
    out4[t] = v;
}

// ---------------------------------------------------------------------------
extern "C" void kernel_launch(void* const* d_in, const int* in_sizes, int n_in,
                              void* d_out, int out_size) {
    const float* src  = (const float*)d_in[0];
    const void*  idxp = d_in[1];
    float*       out  = (float*)d_out;

    const int E        = in_sizes[0] / D_DIM;   // 800000
    const int total_sc = E * D_VEC;             // 12.8M scatter tasks
    const int rowsN    = out_size / D_DIM;      // 50000
    const int total_nm = rowsN * D_VEC;         // 800K normalize tasks

    // zero the (0xAA-poisoned) output — atomics accumulate into it
    cudaMemsetAsync(d_out, 0, (size_t)out_size * sizeof(float), 0);

    k_detect<<<1, 1>>>(idxp);
    k_zero_counts<<<(N_SEG + 255) / 256, 256>>>();
    k_scatter<<<(total_sc + 255) / 256, 256>>>((const float4*)src, idxp, out, total_sc);
    k_norm<<<(total_nm + 255) / 256, 256>>>((float4*)d_out, total_nm);
}